// round 6
// baseline (speedup 1.0000x reference)
#include <cuda_runtime.h>

// CRF forward log-partition. B=512, T=512, L=64.
// Linear-domain scan: v_{t+1}[n] = (sum_p E[n,p] v_t[p]) * exp(emit_t[n]) * scale
// Layout this round: thread (n,h) = (tid>>1, tid&1): ONE tag, 32 prevs (half h).
// All h=0 lanes of a warp read identical v addresses -> LDS broadcast (1 wf/instr);
// half-1 of v lives at +48 floats so the two broadcast groups use disjoint banks.
// Half-combine is a single shfl_xor(1). Renorm every 4 steps (power-of-2 exponent
// trick, lag-1 publish through the per-step barrier). exp(emit) via MUFU at
// prefetch time, distance 2.

#define LOG2E 1.4426950408889634f
#define LN2   0.6931471805599453f

constexpr int L  = 64;
constexpr int TT = 512;

static __device__ __forceinline__ float ex2f(float x) {
    float r; asm("ex2.approx.ftz.f32 %0, %1;" : "=f"(r) : "f"(x)); return r;
}
static __device__ __forceinline__ float lg2f(float x) {
    float r; asm("lg2.approx.ftz.f32 %0, %1;" : "=f"(r) : "f"(x)); return r;
}
static __device__ __forceinline__ unsigned long long pk2(float lo, float hi) {
    unsigned long long r;
    asm("mov.b64 %0, {%1, %2};" : "=l"(r) : "f"(lo), "f"(hi)); return r;
}
static __device__ __forceinline__ void upk2(unsigned long long v, float& lo, float& hi) {
    asm("mov.b64 {%0, %1}, %2;" : "=f"(lo), "=f"(hi) : "l"(v));
}
static __device__ __forceinline__ unsigned long long ffma2(
    unsigned long long a, unsigned long long b, unsigned long long c) {
    unsigned long long d;
    asm("fma.rn.f32x2 %0, %1, %2, %3;" : "=l"(d) : "l"(a), "l"(b), "l"(c)); return d;
}
static __device__ __forceinline__ unsigned long long fadd2(
    unsigned long long a, unsigned long long b) {
    unsigned long long d;
    asm("add.rn.f32x2 %0, %1, %2;" : "=l"(d) : "l"(a), "l"(b)); return d;
}

// v layout per buffer: half0 at [0..32), half1 at [48..80)  (bank-disjoint broadcasts)
constexpr int VBUF = 96;   // floats per buffer (stride multiple of 32 banks)

__global__ __launch_bounds__(128, 4) void crf_fwd(
    const float* __restrict__ emis,   // [B, T, L]
    const float* __restrict__ trans,  // [L, L]  trans[next*L + prev]
    float* __restrict__ out)          // [B]
{
    const int b   = blockIdx.x;
    const int tid = threadIdx.x;
    const int n   = tid >> 1;      // tag 0..63
    const int h   = tid & 1;       // prev-half
    const int w   = tid >> 5;      // warp 0..3
    const unsigned FULL = 0xffffffffu;

    __shared__ __align__(16) float v_sh[2][VBUF];
    __shared__ __align__(16) float red_sh[4];
    __shared__ __align__(16) float sum_sh[4];

    // ---- E row half (1 tag x 32 prevs) into packed-pair registers ----
    unsigned long long E2[16];
    {
        const float4* tr = reinterpret_cast<const float4*>(trans + n * L + h * 32);
        #pragma unroll
        for (int j = 0; j < 8; j++) {
            float4 a = tr[j];
            // exp(-10000) underflows to exactly 0 -> blocked transitions contribute 0
            E2[2 * j]     = pk2(__expf(a.x), __expf(a.y));
            E2[2 * j + 1] = pk2(__expf(a.z), __expf(a.w));
        }
    }
    const float Es = __expf(trans[(L - 1) * L + n]);  // exp(trans[STOP][n])

    // padded index for tag n: n<32 -> n ; n>=32 -> 16+n  (i.e. 48+(n-32))
    const int nst = n + ((n >= 32) ? 16 : 0);

    // ---- init: v0 = delta(START = 62), renorm seed 1.0 ----
    if (tid < L) {
        int m = tid + ((tid >= 32) ? 16 : 0);
        v_sh[0][m] = (tid == L - 2) ? 1.0f : 0.0f;
    }
    if (tid < 4) red_sh[tid] = 1.0f;

    // ---- emission pipeline: exp(emit) at prefetch (distance 2) ----
    const float* eptr = emis + (size_t)b * (TT * L) + n;
    float eA = ex2f(__ldg(eptr) * LOG2E);
    float eB = ex2f(__ldg(eptr + L) * LOG2E);

    int   acc2 = 0;          // accumulated log2 of removed scales
    float v    = 0.0f;
    int   buf  = 0;
    __syncthreads();

    #pragma unroll 1
    for (int it = 0; it < TT / 4; ++it) {
        #pragma unroll
        for (int s = 0; s < 4; ++s) {
            const int t = it * 4 + s;

            float f = eA;
            if (s == 0) {
                // apply renorm measured at previous slot 3 (lag 1 step)
                float4 rv = *reinterpret_cast<const float4*>(red_sh);
                float m = fmaxf(fmaxf(rv.x, rv.y), fmaxf(rv.z, rv.w));
                int ei = (int)((__float_as_uint(m) >> 23) & 0xff);
                float scale = __uint_as_float((unsigned)(253 - ei) << 23); // 2^(126-ei)
                acc2 += ei - 126;
                f *= scale;
            }

            // ---- half dot product: 32 prevs, broadcast LDS.128 reads ----
            const ulonglong2* vv =
                reinterpret_cast<const ulonglong2*>(&v_sh[buf][h * 48]);
            unsigned long long c0, c1, c2, c3;
            {
                ulonglong2 q0 = vv[0], q1 = vv[1];
                c0 = ffma2(q0.x, E2[0], 0ull);
                c1 = ffma2(q0.y, E2[1], 0ull);
                c2 = ffma2(q1.x, E2[2], 0ull);
                c3 = ffma2(q1.y, E2[3], 0ull);
            }
            #pragma unroll
            for (int j = 2; j < 8; j += 2) {
                ulonglong2 q0 = vv[j], q1 = vv[j + 1];
                c0 = ffma2(q0.x, E2[2 * j],     c0);
                c1 = ffma2(q0.y, E2[2 * j + 1], c1);
                c2 = ffma2(q1.x, E2[2 * j + 2], c2);
                c3 = ffma2(q1.y, E2[2 * j + 3], c3);
            }
            float s0;
            { float lo, hi; upk2(fadd2(fadd2(c0, c1), fadd2(c2, c3)), lo, hi); s0 = lo + hi; }

            // combine the two halves (partner lane = xor 1)
            s0 += __shfl_xor_sync(FULL, s0, 1);

            v = s0 * f;

            if (h == 0) v_sh[buf ^ 1][nst] = v;

            if (s == 3) {
                // measure max(v) of THIS step; publish per-warp (read next slot 0)
                float wm = v;
                #pragma unroll
                for (int o = 16; o >= 1; o >>= 1)
                    wm = fmaxf(wm, __shfl_xor_sync(FULL, wm, o));
                if ((tid & 31) == 0) red_sh[w] = wm;
            }

            // prefetch emissions for t+2, exp off the critical path
            {
                int tp = (t + 2 < TT) ? t + 2 : TT - 1;
                float r = __ldg(eptr + (size_t)tp * L);
                eA = eB;
                eB = ex2f(r * LOG2E);
            }

            __syncthreads();
            buf ^= 1;
        }
    }

    // ---- terminal: log(sum_n v[n]*exp(trans[STOP][n])) + acc2*ln2 ----
    float term = (h == 0) ? v * Es : 0.0f;     // zero dup half to avoid double count
    #pragma unroll
    for (int o = 16; o >= 1; o >>= 1) term += __shfl_xor_sync(FULL, term, o);
    if ((tid & 31) == 0) sum_sh[w] = term;
    __syncthreads();
    if (tid == 0) {
        float tot = sum_sh[0] + sum_sh[1] + sum_sh[2] + sum_sh[3];
        out[b] = (lg2f(tot) + (float)acc2) * LN2;
    }
}

extern "C" void kernel_launch(void* const* d_in, const int* in_sizes, int n_in,
                              void* d_out, int out_size) {
    const float* emis  = (const float*)d_in[0];   // [B, T, L] float32
    const float* trans = (const float*)d_in[1];   // [L, L] float32
    float* out = (float*)d_out;                   // [B] float32
    int B = in_sizes[0] / (TT * L);
    crf_fwd<<<B, 128>>>(emis, trans, out);
}